// round 14
// baseline (speedup 1.0000x reference)
#include <cuda_runtime.h>
#include <cuda_bf16.h>
#include <math.h>
#include <stdint.h>

#define NB 64
#define CB 256
#define SB 64
#define PB 16
#define KCL 4
#define RT (NB*PB*SB)          // 65536 total rows (b = n*16+p, s)

// ------------------------------------------------------------------ globals
__device__ float         g_xb[(size_t)RT*CB];     // X fp32 (b,s,c) exact
__device__ __nv_bfloat16 g_xh[(size_t)RT*CB];     // X hi
__device__ __nv_bfloat16 g_xl[(size_t)RT*CB];     // X lo
__device__ __nv_bfloat16 g_ph[(size_t)RT*768];    // Q|K|V hi (Q pre-scaled by 1/8)
__device__ __nv_bfloat16 g_pl[(size_t)RT*768];    // Q|K|V lo
__device__ __nv_bfloat16 g_oh[(size_t)RT*CB];     // attn out hi
__device__ __nv_bfloat16 g_ol[(size_t)RT*CB];     // attn out lo
__device__ __nv_bfloat16 g_wh[1024*CB];           // weights hi: rows 0..767 = Wq|Wk|Wv^T, 768..1023 = Wo^T   [n][k]
__device__ __nv_bfloat16 g_wl[1024*CB];           // lo
__device__ float         g_biasv[1024];           // bq|bk|bv|bo
__device__ float         g_clu[PB*NB*KCL*CB];
__device__ unsigned char g_hidx[PB*NB*SB];

// ------------------------------------------------------------------ helpers
__device__ __forceinline__ uint32_t smem_u32(const void* p) {
    uint32_t a;
    asm("{ .reg .u64 t; cvta.to.shared.u64 t, %1; cvt.u32.u64 %0, t; }" : "=r"(a) : "l"(p));
    return a;
}
__device__ __forceinline__ void ldsm4(uint32_t a, uint32_t& r0, uint32_t& r1, uint32_t& r2, uint32_t& r3) {
    asm volatile("ldmatrix.sync.aligned.m8n8.x4.shared.b16 {%0,%1,%2,%3}, [%4];"
        : "=r"(r0), "=r"(r1), "=r"(r2), "=r"(r3) : "r"(a));
}
__device__ __forceinline__ void ldsm4t(uint32_t a, uint32_t& r0, uint32_t& r1, uint32_t& r2, uint32_t& r3) {
    asm volatile("ldmatrix.sync.aligned.m8n8.x4.trans.shared.b16 {%0,%1,%2,%3}, [%4];"
        : "=r"(r0), "=r"(r1), "=r"(r2), "=r"(r3) : "r"(a));
}
__device__ __forceinline__ void mma16816(float* d, const uint32_t* a, uint32_t b0, uint32_t b1) {
    asm volatile("mma.sync.aligned.m16n8k16.row.col.f32.bf16.bf16.f32 "
        "{%0,%1,%2,%3}, {%4,%5,%6,%7}, {%8,%9}, {%0,%1,%2,%3};"
        : "+f"(d[0]), "+f"(d[1]), "+f"(d[2]), "+f"(d[3])
        : "r"(a[0]), "r"(a[1]), "r"(a[2]), "r"(a[3]), "r"(b0), "r"(b1));
}
__device__ __forceinline__ void cp16(uint32_t sa, const void* ga) {
    asm volatile("cp.async.cg.shared.global [%0], [%1], 16;" :: "r"(sa), "l"(ga));
}
__device__ __forceinline__ void split2(float x, float y, uint32_t& hi, uint32_t& lo) {
    __nv_bfloat16 hx = __float2bfloat16(x), hy = __float2bfloat16(y);
    __nv_bfloat16 lx = __float2bfloat16(x - __bfloat162float(hx));
    __nv_bfloat16 ly = __float2bfloat16(y - __bfloat162float(hy));
    __nv_bfloat162 H; H.x = hx; H.y = hy;
    __nv_bfloat162 L; L.x = lx; L.y = ly;
    hi = *(uint32_t*)&H; lo = *(uint32_t*)&L;
}

// ------------------------------------------------------------------ K0: transpose + bf16 split
__global__ __launch_bounds__(256) void k0_transpose(const float* __restrict__ x) {
    extern __shared__ float tile[];          // [(s*16+p)][17]
    const int cchunk = blockIdx.x, n = blockIdx.y;
    const int t = threadIdx.x;
    const int c0 = cchunk * 16;
    #pragma unroll
    for (int it = 0; it < 16; it++) {
        int idx = it * 256 + t;
        int ci = idx >> 8;
        int rem = idx & 255;
        int s = rem >> 2;
        int p4 = rem & 3;
        const float4 v = *(const float4*)(x + (((size_t)n*CB + c0 + ci)*SB + s)*PB + p4*4);
        int base = (s*16 + p4*4)*17 + ci;
        tile[base] = v.x; tile[base+17] = v.y; tile[base+34] = v.z; tile[base+51] = v.w;
    }
    __syncthreads();
    #pragma unroll
    for (int it = 0; it < 8; it++) {
        int idx = it * 256 + t;              // 2048: (s,p,vec8)
        int vec = idx & 1;
        int pr = idx >> 1;
        int s = pr >> 4, p = pr & 15;
        int base = (s*16 + p)*17 + vec*8;
        __align__(16) float f[8];
        __align__(16) __nv_bfloat16 hi[8];
        __align__(16) __nv_bfloat16 lo[8];
        #pragma unroll
        for (int u = 0; u < 8; u++) {
            float v = tile[base + u];
            f[u] = v;
            hi[u] = __float2bfloat16(v);
            lo[u] = __float2bfloat16(v - __bfloat162float(hi[u]));
        }
        size_t off = (((size_t)n*16 + p)*64 + s)*256 + c0 + vec*8;
        *(uint4*)(g_xb + off)     = *(uint4*)f;
        *(uint4*)(g_xb + off + 4) = *(uint4*)(f + 4);
        *(uint4*)(g_xh + off) = *(uint4*)hi;
        *(uint4*)(g_xl + off) = *(uint4*)lo;
    }
}

// ------------------------------------------------------------------ K_wprep: smem-tiled transpose
__global__ __launch_bounds__(256) void k_wprep(
    const float* __restrict__ Wq, const float* __restrict__ Wk,
    const float* __restrict__ Wv, const float* __restrict__ Wo,
    const float* __restrict__ bq, const float* __restrict__ bk,
    const float* __restrict__ bv, const float* __restrict__ bo)
{
    __shared__ float tile[64*68];
    const int bx = blockIdx.x;               // 64 blocks
    const int mat = bx >> 4, tl = bx & 15;
    const int kt = (tl >> 2) << 6, nt = (tl & 3) << 6;
    const float* W = (mat == 0) ? Wq : (mat == 1) ? Wk : (mat == 2) ? Wv : Wo;
    const int t = threadIdx.x;
    #pragma unroll
    for (int it = 0; it < 4; it++) {
        int v = it*256 + t;
        int r = v >> 4, c4 = (v & 15) << 2;
        float4 val = *(const float4*)(W + (size_t)(kt + r)*256 + nt + c4);
        tile[(c4+0)*68 + r] = val.x;
        tile[(c4+1)*68 + r] = val.y;
        tile[(c4+2)*68 + r] = val.z;
        tile[(c4+3)*68 + r] = val.w;
    }
    __syncthreads();
    #pragma unroll
    for (int it = 0; it < 2; it++) {
        int v = it*256 + t;
        int n = v >> 3, k8 = (v & 7) << 3;
        __align__(16) __nv_bfloat16 hi[8];
        __align__(16) __nv_bfloat16 lo[8];
        #pragma unroll
        for (int u = 0; u < 8; u++) {
            float w = tile[n*68 + k8 + u];
            hi[u] = __float2bfloat16(w);
            lo[u] = __float2bfloat16(w - __bfloat162float(hi[u]));
        }
        size_t off = (size_t)(mat*256 + nt + n)*256 + kt + k8;
        *(uint4*)(g_wh + off) = *(uint4*)hi;
        *(uint4*)(g_wl + off) = *(uint4*)lo;
    }
    if (tl == 0) {
        const float* bias = (mat == 0) ? bq : (mat == 1) ? bk : (mat == 2) ? bv : bo;
        g_biasv[mat*256 + t] = bias[t];
    }
}

// ------------------------------------------------------------------ K1: instnorm + argmax assignment
__global__ __launch_bounds__(256) void k1_assign(const float* __restrict__ proto) {
    extern __shared__ float sm1[];
    float* xs = sm1;               // 64*257
    float* pn = xs + 64*257;       // 4*257
    float* mu = pn + 4*257;        // 256
    float* rv = mu + 256;          // 256
    __shared__ float nrm[4];
    const int b = blockIdx.x;
    const int n = b >> 4, p = b & 15;
    const int t = threadIdx.x;

    #pragma unroll
    for (int it = 0; it < 4; it++) {
        int i = it*256 + t; int k = i >> 8; int c = i & 255;
        pn[k*257 + c] = proto[((size_t)p*4 + k)*256 + c];
    }
    __syncthreads();
    if (t < 128) {
        int k = t >> 5, lane = t & 31; float s = 0.f;
        #pragma unroll
        for (int j = 0; j < 8; j++) { float v = pn[k*257 + lane + j*32]; s += v*v; }
        #pragma unroll
        for (int o = 16; o > 0; o >>= 1) s += __shfl_down_sync(0xffffffffu, s, o);
        if (lane == 0) nrm[k] = rsqrtf(s);
    }
    __syncthreads();
    #pragma unroll
    for (int it = 0; it < 4; it++) {
        int i = it*256 + t; int k = i >> 8; int c = i & 255;
        pn[k*257 + c] *= nrm[k];
    }
    const float* xg = g_xb + (size_t)b * SB * CB;
    for (int it = 0; it < 64; it++) {
        int i = it*256 + t; int s = i >> 8; int c = i & 255;
        xs[s*257 + c] = xg[i];
    }
    __syncthreads();
    {
        int c = t; float sum = 0.f;
        #pragma unroll 8
        for (int s = 0; s < 64; s++) sum += xs[s*257 + c];
        float m = sum * (1.f/64.f);
        float sq = 0.f;
        #pragma unroll 8
        for (int s = 0; s < 64; s++) { float d = xs[s*257 + c] - m; sq += d*d; }
        mu[c] = m;
        rv[c] = rsqrtf(sq * (1.f/64.f) + 1e-5f);
    }
    __syncthreads();
    {
        int s = t >> 2, k = t & 3;
        float acc = 0.f;
        #pragma unroll 8
        for (int c = 0; c < 256; c++)
            acc += (xs[s*257 + c] - mu[c]) * rv[c] * pn[k*257 + c];
        float a1 = __shfl_down_sync(0xffffffffu, acc, 1);
        float a2 = __shfl_down_sync(0xffffffffu, acc, 2);
        float a3 = __shfl_down_sync(0xffffffffu, acc, 3);
        if (k == 0) {
            int bi = 0; float bv = acc;
            if (a1 > bv) { bv = a1; bi = 1; }
            if (a2 > bv) { bv = a2; bi = 2; }
            if (a3 > bv) { bv = a3; bi = 3; }
            g_hidx[((size_t)p*64 + n)*64 + s] = (unsigned char)bi;
        }
    }
}

// ------------------------------------------------------------------ K2: mode over parts
__global__ void k2_mode(float* __restrict__ out, int doWrite) {
    int id = blockIdx.x * 256 + threadIdx.x;
    int n = id >> 6, s = id & 63;
    int cnt[4] = {0,0,0,0};
    #pragma unroll
    for (int p = 0; p < 16; p++) cnt[g_hidx[((size_t)p*64 + n)*64 + s]]++;
    int bi = 0, bv = cnt[0];
    if (cnt[1] > bv) { bv = cnt[1]; bi = 1; }
    if (cnt[2] > bv) { bv = cnt[2]; bi = 2; }
    if (cnt[3] > bv) { bv = cnt[3]; bi = 3; }
    if (doWrite) out[NB*CB*PB + id] = (float)bi;
}

// ------------------------------------------------------------------ k_gemm: occupancy-first warp-MMA (2 CTAs/SM)
#define KCH 32
#define LDC 40
#define CTILE (128*LDC*2)       // 10240 bytes per array
#define STG (4*CTILE)           // 40960
#define GEMM_SMEM (2*STG)       // 81920
#define YLD 132

__device__ __forceinline__ void load_stage(const __nv_bfloat16* __restrict__ Ah,
        const __nv_bfloat16* __restrict__ Al, size_t arow0,
        int brow0, int k0, uint32_t st, int t) {
    #pragma unroll
    for (int it = 0; it < 2; it++) {
        int v = it*256 + t;                  // 512: 128 rows x 4 vec8
        int r = v >> 2, kv = (v & 3) << 3;
        uint32_t so = (uint32_t)(r*LDC + kv)*2;
        size_t aoff = (arow0 + r)*256 + k0 + kv;
        size_t boff = (size_t)(brow0 + r)*256 + k0 + kv;
        cp16(st + so,            Ah + aoff);
        cp16(st + CTILE + so,    Al + aoff);
        cp16(st + 2*CTILE + so,  g_wh + boff);
        cp16(st + 3*CTILE + so,  g_wl + boff);
    }
}

__global__ __launch_bounds__(256, 2) void k_gemm(int mode, int mbase) {
    extern __shared__ char sm[];
    const uint32_t sb = smem_u32(sm);
    const int t = threadIdx.x;
    const int w = t >> 5, lane = t & 31;
    const int m0 = (mbase + blockIdx.x) * 128;
    const int wy = w >> 1, wx = w & 1;
    const int m_base = wy*32, n_base = wx*64;
    __shared__ unsigned char sidx[128];

    if (mode == 1 && t < 128) {
        int b = (m0 >> 6) + (t >> 6);
        sidx[t] = g_hidx[((size_t)(b & 15)*64 + (b >> 4))*64 + (t & 63)];
    }

    const __nv_bfloat16* Ah_src = (mode == 0) ? g_xh : g_oh;
    const __nv_bfloat16* Al_src = (mode == 0) ? g_xl : g_ol;
    const int NBLK = (mode == 0) ? 6 : 2;
    const int bbase = (mode == 0) ? 0 : 768;

    const int li = lane >> 3, lr = lane & 7;
    const int a_row = (li & 1)*8 + lr, a_kof = (li >> 1)*8;
    const int b_row = (li >> 1)*8 + lr, b_kof = (li & 1)*8;

    float* Ys = (float*)sm;

    for (int nb = 0; nb < NBLK; nb++) {
        const int brow0 = bbase + nb*128;
        __syncthreads();
        load_stage(Ah_src, Al_src, (size_t)m0, brow0, 0, sb, t);
        asm volatile("cp.async.commit_group;" ::: "memory");

        float acc[2][8][4];
        #pragma unroll
        for (int i = 0; i < 2; i++)
            #pragma unroll
            for (int j = 0; j < 8; j++)
                #pragma unroll
                for (int q = 0; q < 4; q++) acc[i][j][q] = 0.f;

        #pragma unroll
        for (int c = 0; c < 8; c++) {
            if (c < 7) {
                load_stage(Ah_src, Al_src, (size_t)m0, brow0, (c + 1)*KCH,
                           sb + ((c + 1) & 1)*STG, t);
                asm volatile("cp.async.commit_group;" ::: "memory");
                asm volatile("cp.async.wait_group 1;" ::: "memory");
            } else {
                asm volatile("cp.async.wait_group 0;" ::: "memory");
            }
            __syncthreads();
            const uint32_t st = sb + (c & 1)*STG;
            #pragma unroll
            for (int ks = 0; ks < 2; ks++) {
                const int kk = ks*16;
                uint32_t ah[2][4], al[2][4];
                #pragma unroll
                for (int mf = 0; mf < 2; mf++) {
                    uint32_t off = (uint32_t)((m_base + mf*16 + a_row)*LDC + kk + a_kof)*2;
                    ldsm4(st + off, ah[mf][0], ah[mf][1], ah[mf][2], ah[mf][3]);
                    ldsm4(st + CTILE + off, al[mf][0], al[mf][1], al[mf][2], al[mf][3]);
                }
                #pragma unroll
                for (int nbf = 0; nbf < 4; nbf++) {
                    uint32_t off = (uint32_t)((n_base + nbf*16 + b_row)*LDC + kk + b_kof)*2;
                    uint32_t bh0, bh1, bh2, bh3, bl0, bl1, bl2, bl3;
                    ldsm4(st + 2*CTILE + off, bh0, bh1, bh2, bh3);
                    ldsm4(st + 3*CTILE + off, bl0, bl1, bl2, bl3);
                    #pragma unroll
                    for (int mf = 0; mf < 2; mf++) {
                        mma16816(acc[mf][nbf*2],     ah[mf], bh0, bh1);
                        mma16816(acc[mf][nbf*2 + 1], ah[mf], bh2, bh3);
                        mma16816(acc[mf][nbf*2],     ah[mf], bl0, bl1);
                        mma16816(acc[mf][nbf*2 + 1], ah[mf], bl2, bl3);
                        mma16816(acc[mf][nbf*2],     al[mf], bh0, bh1);
                        mma16816(acc[mf][nbf*2 + 1], al[mf], bh2, bh3);
                    }
                }
            }
            __syncthreads();
        }

        {
            const int mr = lane >> 2, nc = (lane & 3)*2;
            #pragma unroll
            for (int mf = 0; mf < 2; mf++)
                #pragma unroll
                for (int nf = 0; nf < 8; nf++) {
                    int m = m_base + mf*16 + mr;
                    int n = n_base + nf*8 + nc;
                    float b0 = g_biasv[brow0 + n], b1 = g_biasv[brow0 + n + 1];
                    Ys[m*YLD + n]           = acc[mf][nf][0] + b0;
                    Ys[m*YLD + n + 1]       = acc[mf][nf][1] + b1;
                    Ys[(m + 8)*YLD + n]     = acc[mf][nf][2] + b0;
                    Ys[(m + 8)*YLD + n + 1] = acc[mf][nf][3] + b1;
                }
        }
        __syncthreads();

        if (mode == 0) {
            const float qscale = (nb < 2) ? 0.125f : 1.f;
            for (int v = t; v < 2048; v += 256) {       // 128 rows x 16 vec8
                int r = v >> 4, c8 = (v & 15) << 3;
                uint32_t hi4[4], lo4[4];
                #pragma unroll
                for (int u = 0; u < 4; u++) {
                    float fa = Ys[r*YLD + c8 + 2*u]     * qscale;
                    float fb = Ys[r*YLD + c8 + 2*u + 1] * qscale;
                    split2(fa, fb, hi4[u], lo4[u]);
                }
                size_t off = (size_t)(m0 + r)*768 + nb*128 + c8;
                *(uint4*)(g_ph + off) = *(uint4*)hi4;
                *(uint4*)(g_pl + off) = *(uint4*)lo4;
            }
        } else {
            for (int v = t; v < 4096; v += 256) {
                int r = v >> 5, c4 = (v & 31) << 2;
                float4 rx = *(const float4*)(g_xb + (size_t)(m0 + r)*256 + nb*128 + c4);
                Ys[r*YLD + c4]     += rx.x;
                Ys[r*YLD + c4 + 1] += rx.y;
                Ys[r*YLD + c4 + 2] += rx.z;
                Ys[r*YLD + c4 + 3] += rx.w;
            }
            __syncthreads();
            for (int id = t; id < 1024; id += 256) {
                int bl = id >> 9, j = (id >> 7) & 3, c = id & 127;
                float m = -1e30f;
                #pragma unroll 8
                for (int s = 0; s < 64; s++) {
                    float v = (sidx[bl*64 + s] == j) ? Ys[(bl*64 + s)*YLD + c] : 0.f;
                    m = fmaxf(m, v);
                }
                int b = (m0 >> 6) + bl;
                int n = b >> 4, p = b & 15;
                g_clu[((size_t)p*64 + n)*1024 + j*256 + nb*128 + c] = m;
            }
        }
    }
}

// ------------------------------------------------------------------ K_attn: HMMA attention per (b, h), 128 threads
// smem 4 tiles: Q(hi,lo)+K(hi,lo); V(hi,lo) reuses Q region after scores.
#define LDV 72
#define AT_TILE (64*LDV*2)      // 9216
#define ATTN_SMEM (4*AT_TILE)   // 36864

__global__ __launch_bounds__(128) void k_attn(int boff) {
    extern __shared__ char sma[];
    const uint32_t sb = smem_u32(sma);
    const uint32_t sQh = sb, sQl = sb + AT_TILE, sKh = sb + 2*AT_TILE, sKl = sb + 3*AT_TILE;
    const uint32_t sVh = sb, sVl = sb + AT_TILE;      // reuse Q region
    const int bid = blockIdx.x + boff;
    const int b = bid >> 2, h = bid & 3;
    const int t = threadIdx.x;
    const int w = t >> 5, lane = t & 31;
    const size_t rbase = (size_t)b * 64;

    // load split Q,K tiles
    #pragma unroll
    for (int q = 0; q < 2; q++) {
        for (int idx = t; idx < 512; idx += 128) {
            int r = idx >> 3, kv = (idx & 7) << 3;
            size_t go = (rbase + r)*768 + q*256 + h*64 + kv;
            uint32_t so = (uint32_t)(r*LDV + kv)*2;
            cp16(sb + (2*q)*AT_TILE + so,     g_ph + go);
            cp16(sb + (2*q + 1)*AT_TILE + so, g_pl + go);
        }
    }
    asm volatile("cp.async.commit_group;" ::: "memory");
    asm volatile("cp.async.wait_group 0;" ::: "memory");
    __syncthreads();

    const int r0 = w * 16;
    const int li = lane >> 3, lr = lane & 7;
    const int t_row = (li & 1)*8 + lr, t_col = (li >> 1)*8;
    const int b_row = (li >> 1)*8 + lr, b_col = (li & 1)*8;

    // ---- scores = (Q/8) K^T (3-term split) ----
    float sc[4][8];
    #pragma unroll
    for (int i = 0; i < 4; i++)
        #pragma unroll
        for (int j = 0; j < 8; j++) sc[i][j] = 0.f;

    #pragma unroll
    for (int kb = 0; kb < 4; kb++) {
        uint32_t aoff = (uint32_t)((r0 + t_row)*LDV + kb*16 + t_col)*2;
        uint32_t qh[4], ql[4];
        ldsm4(sQh + aoff, qh[0], qh[1], qh[2], qh[3]);
        ldsm4(sQl + aoff, ql[0], ql[1], ql[2], ql[3]);
        #pragma unroll
        for (int nb = 0; nb < 4; nb++) {
            uint32_t boff2 = (uint32_t)((nb*16 + b_row)*LDV + kb*16 + b_col)*2;
            uint32_t kh0, kh1, kh2, kh3, kl0, kl1, kl2, kl3;
            ldsm4(sKh + boff2, kh0, kh1, kh2, kh3);
            ldsm4(sKl + boff2, kl0, kl1, kl2, kl3);
            mma16816(sc[nb],     qh, kh0, kh1);
            mma16816(sc[nb] + 4, qh, kh2, kh3);
            mma16816(sc[nb],     qh, kl0, kl1);
            mma16816(sc[nb] + 4, qh, kl2, kl3);
            mma16816(sc[nb],     ql, kh0, kh1);
            mma16816(sc[nb] + 4, ql, kh2, kh3);
        }
    }
    __syncthreads();                         // all warps done reading Q (V overwrites it)

    // issue V load now; softmax (register-only) hides the latency
    for (int idx = t; idx < 512; idx += 128) {
        int r = idx >> 3, kv = (idx & 7) << 3;
        size_t go = (rbase + r)*768 + 2*256 + h*64 + kv;
        uint32_t so = (uint32_t)(r*LDV + kv)*2;
        cp16(sVh + so, g_ph + go);
        cp16(sVl + so, g_pl + go);
    }
    asm volatile("cp.async.commit_group;" ::: "memory");

    // ---- causal softmax in registers ----
    {
        const int r = lane >> 2, q2 = (lane & 3)*2;
        const int gr0 = r0 + r, gr1 = gr0 + 8;
        float m0 = -1e30f, m1 = -1e30f;
        #pragma unroll
        for (int nb = 0; nb < 4; nb++) {
            int c0 = nb*16 + q2, c8 = c0 + 8;
            if (c0     > gr0) sc[nb][0] = -1e30f;
            if (c0 + 1 > gr0) sc[nb][1] = -1e30f;
            if (c8     > gr0) sc[nb][4] = -1e30f;
            if (c8 + 1 > gr0) sc[nb][5] = -1e30f;
            if (c0     > gr1) sc[nb][2] = -1e30f;
            if (c0 + 1 > gr1) sc[nb][3] = -1e30f;
            if (c8     > gr1) sc[nb][6] = -1e30f;
            if (c8 + 1 > gr1) sc[nb][7] = -1e30f;
            m0 = fmaxf(m0, fmaxf(fmaxf(sc[nb][0], sc[nb][1]), fmaxf(sc[nb][4], sc[nb][5])));
            m1 = fmaxf(m1, fmaxf(fmaxf(sc[nb][2], sc[nb][3]), fmaxf(sc[nb][6], sc[nb][7])));
        }
        #pragma unroll
        for (int o = 1; o < 4; o <<= 1) {
            m0 = fmaxf(m0, __shfl_xor_sync(0xffffffffu, m0, o));
            m1 = fmaxf(m1, __shfl_xor_sync(0xffffffffu, m1, o));
        }
        float s0 = 0.f, s1 = 0.f;
        #pragma unroll
        for (int nb = 0; nb < 4; nb++) {
            sc[nb][0] = __expf(sc[nb][0] - m0); s0 += sc[nb][0];
            sc[nb][1] = __expf(sc[nb][1] - m0); s0 += sc[nb][1];
            sc[nb][4] = __expf(sc[nb][4] - m0); s0 += sc[nb][4];
            sc[nb][5] = __expf(sc[nb][5] - m0); s0 += sc[nb][5];
            sc[nb][2] = __expf(sc[nb][2] - m1); s1 += sc[nb][2];
            sc[nb][3] = __expf(sc[nb][3] - m1); s1 += sc[nb][3];
            sc[nb][6] = __expf(sc[nb][6] - m1); s1 += sc[nb][6];
            sc[nb][7] = __expf(sc[nb][7] - m1); s1 += sc[nb][7];
        }
        #pragma unroll
        for (int o = 1; o < 4; o <<= 1) {
            s0 += __shfl_xor_sync(0xffffffffu, s0, o);
            s1 += __shfl_xor_sync(0xffffffffu, s1, o);
        }
        float i0 = 1.f / s0, i1 = 1.f / s1;
        #pragma unroll
        for (int nb = 0; nb < 4; nb++) {
            sc[nb][0] *= i0; sc[nb][1] *= i0; sc[nb][4] *= i0; sc[nb][5] *= i0;
            sc[nb][2] *= i1; sc[nb][3] *= i1; sc[nb][6] *= i1; sc[nb][7] *= i1;
        }
    }

    asm volatile("cp.async.wait_group 0;" ::: "memory");
    __syncthreads();                         // V tiles ready

    // ---- O = P V ----
    float o[4][8];
    #pragma unroll
    for (int i = 0; i < 4; i++)
        #pragma unroll
        for (int j = 0; j < 8; j++) o[i][j] = 0.f;

    #pragma unroll
    for (int kb = 0; kb < 4; kb++) {
        uint32_t ph[4], pl[4];
        split2(sc[kb][0], sc[kb][1], ph[0], pl[0]);
        split2(sc[kb][2], sc[kb][3], ph[1], pl[1]);
        split2(sc[kb][4], sc[kb][5], ph[2], pl[2]);
        split2(sc[kb][6], sc[kb][7], ph[3], pl[3]);
        #pragma unroll
        for (int nbo = 0; nbo < 4; nbo++) {
            uint32_t voff = (uint32_t)((kb*16 + t_row)*LDV + nbo*16 + t_col)*2;
            uint32_t vh0, vh1, vh2, vh3, vl0, vl1, vl2, vl3;
            ldsm4t(sVh + voff, vh0, vh1, vh2, vh3);
            ldsm4t(sVl + voff, vl0, vl1, vl2, vl3);
            mma16816(o[nbo],     ph, vh0, vh1);
            mma16816(o[nbo] + 4, ph, vh2, vh3);
            mma16816(o[nbo],     ph, vl0, vl1);
            mma16816(o[nbo] + 4, ph, vl2, vl3);
            mma16816(o[nbo],     pl, vh0, vh1);
            mma16816(o[nbo] + 4, pl, vh2, vh3);
        }
    }

    {
        const int r = lane >> 2, q2 = (lane & 3)*2;
        const size_t base0 = (rbase + r0 + r)*256 + h*64;
        const size_t base1 = base0 + 8*256;
        #pragma unroll
        for (int nbo = 0; nbo < 4; nbo++) {
            int c = nbo*16 + q2;
            uint32_t hi, lo;
            split2(o[nbo][0], o[nbo][1], hi, lo);
            *(uint32_t*)(g_oh + base0 + c) = hi;     *(uint32_t*)(g_ol + base0 + c) = lo;
            split2(o[nbo][4], o[nbo][5], hi, lo);
            *(uint32_t*)(g_oh + base0 + c + 8) = hi; *(uint32_t*)(g_ol + base0 + c + 8) = lo;
            split2(o[nbo][2], o[nbo][3], hi, lo);
            *(uint32_t*)(g_oh + base1 + c) = hi;     *(uint32_t*)(g_ol + base1 + c) = lo;
            split2(o[nbo][6], o[nbo][7], hi, lo);
            *(uint32_t*)(g_oh + base1 + c + 8) = hi; *(uint32_t*)(g_ol + base1 + c + 8) = lo;
        }
    }
}

// ------------------------------------------------------------------ K4: per-part FC  out[n,o,p]
__global__ __launch_bounds__(256) void k4_fc(const float* __restrict__ fc, float* __restrict__ out) {
    __shared__ float As[64*68];
    __shared__ float Bs[64*64];
    const int p = blockIdx.x, ot = blockIdx.y;
    const int t = threadIdx.x;
    const int tx = t & 15, ty = t >> 4;
    const int o0 = tx*4, n0 = ty*4;
    float acc[4][4] = {};
    for (int k0 = 0; k0 < 1024; k0 += 64) {
        __syncthreads();
        #pragma unroll
        for (int it = 0; it < 4; it++) {
            int idx = it*256 + t;
            int nn = idx >> 4, k4 = idx & 15;
            *(float4*)(As + nn*68 + k4*4) =
                *(const float4*)(g_clu + ((size_t)p*64 + nn)*1024 + k0 + k4*4);
        }
        #pragma unroll
        for (int it = 0; it < 4; it++) {
            int idx = it*256 + t;
            int kk = idx >> 4, d4 = idx & 15;
            *(float4*)(Bs + kk*64 + d4*4) =
                *(const float4*)(fc + ((size_t)p*1024 + k0 + kk)*256 + ot*64 + d4*4);
        }
        __syncthreads();
        #pragma unroll 4
        for (int kk = 0; kk < 64; kk++) {
            float a[4];
            #pragma unroll
            for (int ii = 0; ii < 4; ii++) a[ii] = As[(n0+ii)*68 + kk];
            float4 bv = *(const float4*)(Bs + kk*64 + o0);
            float bj[4] = {bv.x, bv.y, bv.z, bv.w};
            #pragma unroll
            for (int ii = 0; ii < 4; ii++)
                #pragma unroll
                for (int jj = 0; jj < 4; jj++) acc[ii][jj] += a[ii]*bj[jj];
        }
    }
    #pragma unroll
    for (int ii = 0; ii < 4; ii++)
        #pragma unroll
        for (int jj = 0; jj < 4; jj++)
            out[((size_t)(n0+ii)*256 + ot*64 + o0 + jj)*16 + p] = acc[ii][jj];
}

// ------------------------------------------------------------------ launch: concurrent halves (3 worker streams)
extern "C" void kernel_launch(void* const* d_in, const int* in_sizes, int n_in,
                              void* d_out, int out_size) {
    const float* x     = (const float*)d_in[0];
    const float* proto = (const float*)d_in[1];
    const float* Wq    = (const float*)d_in[2];
    const float* bq    = (const float*)d_in[3];
    const float* Wk    = (const float*)d_in[4];
    const float* bk    = (const float*)d_in[5];
    const float* Wv    = (const float*)d_in[6];
    const float* bv    = (const float*)d_in[7];
    const float* Wo    = (const float*)d_in[8];
    const float* bo    = (const float*)d_in[9];
    const float* fc    = (const float*)d_in[10];
    float* out = (float*)d_out;

    cudaFuncSetAttribute(k0_transpose, cudaFuncAttributeMaxDynamicSharedMemorySize, 69632);
    cudaFuncSetAttribute(k1_assign,    cudaFuncAttributeMaxDynamicSharedMemorySize, 73728);
    cudaFuncSetAttribute(k_gemm,       cudaFuncAttributeMaxDynamicSharedMemorySize, GEMM_SMEM);
    cudaFuncSetAttribute(k_attn,       cudaFuncAttributeMaxDynamicSharedMemorySize, ATTN_SMEM);

    cudaStream_t s1, s2;
    cudaStreamCreate(&s1);
    cudaStreamCreate(&s2);
    cudaEvent_t eFork, eW, e0, eK, eG0A, eG0B, eS2;
    cudaEventCreateWithFlags(&eFork, cudaEventDisableTiming);
    cudaEventCreateWithFlags(&eW,    cudaEventDisableTiming);
    cudaEventCreateWithFlags(&e0,    cudaEventDisableTiming);
    cudaEventCreateWithFlags(&eK,    cudaEventDisableTiming);
    cudaEventCreateWithFlags(&eG0A,  cudaEventDisableTiming);
    cudaEventCreateWithFlags(&eG0B,  cudaEventDisableTiming);
    cudaEventCreateWithFlags(&eS2,   cudaEventDisableTiming);

    int wtail = (out_size >= NB*CB*PB + NB*SB) ? 1 : 0;

    // s1: weight prep (parallel with k0)
    cudaEventRecord(eFork, 0);
    cudaStreamWaitEvent(s1, eFork, 0);
    k_wprep<<<64, 256, 0, s1>>>(Wq, Wk, Wv, Wo, bq, bk, bv, bo);

    k0_transpose<<<dim3(16, 64), 256, 69632>>>(x);
    cudaEventRecord(e0, 0);

    // s2: assignment path (overlaps gemm0)
    cudaStreamWaitEvent(s2, e0, 0);
    k1_assign<<<NB*PB, 256, (64*257 + 4*257 + 512) * sizeof(float), s2>>>(proto);
    cudaEventRecord(eK, s2);

    // gemm0 halves run CONCURRENTLY: A on main, B on s1 (s1 already ordered after wprep)
    cudaEventRecord(eW, s1);
    cudaStreamWaitEvent(s1, e0, 0);                  // g_xh/g_xl ready
    cudaStreamWaitEvent(0, eW, 0);                   // weights ready for A half
    k_gemm<<<256, 256, GEMM_SMEM>>>(0, 0);           // gemm0 A (b 0..511)       [main]
    cudaEventRecord(eG0A, 0);
    k_gemm<<<256, 256, GEMM_SMEM, s1>>>(0, 256);     // gemm0 B (b 512..1023)    [s1, concurrent]
    cudaEventRecord(eG0B, s1);

    // s2: attnA + gemm1A (overlaps gemm0B tail and attnB)
    cudaStreamWaitEvent(s2, eG0A, 0);
    k_attn<<<2048, 128, ATTN_SMEM, s2>>>(0);         // attn A
    k_gemm<<<256, 256, GEMM_SMEM, s2>>>(1, 0);       // gemm1 A (k1 earlier on s2 orders g_hidx)
    cudaEventRecord(eS2, s2);

    // main: attnB + gemm1B
    cudaStreamWaitEvent(0, eG0B, 0);
    k_attn<<<2048, 128, ATTN_SMEM>>>(2048);          // attn B
    cudaStreamWaitEvent(0, eK, 0);                   // g_hidx ready
    k_gemm<<<256, 256, GEMM_SMEM>>>(1, 256);         // gemm1 B
    cudaStreamWaitEvent(0, eS2, 0);                  // join gemm1 A
    k4_fc<<<dim3(16, 4), 256>>>(fc, out);
    k2_mode<<<16, 256>>>(out, wtail);                // tail write; no downstream deps

    cudaEventDestroy(eFork);
    cudaEventDestroy(eW);
    cudaEventDestroy(e0);
    cudaEventDestroy(eK);
    cudaEventDestroy(eG0A);
    cudaEventDestroy(eG0B);
    cudaEventDestroy(eS2);
    cudaStreamDestroy(s1);
    cudaStreamDestroy(s2);
}